// round 5
// baseline (speedup 1.0000x reference)
#include <cuda_runtime.h>
#include <cuda_bf16.h>

#define NBINS 256
#define NIMG  96
#define BATCH 24
#define HDIM  512
#define WDIM  512
#define CHUNK 16
#define PI_F  3.14159265358979323846f

#define TILES_PER_IMG (128 * 128)
#define BUF_FLOATS (4 * BATCH * TILES_PER_IMG * 4)   // 6.29M floats = 25.2 MB

// double-buffered parity-tile scratch; zero-initialized at load, every call
// restores it to zero (merge zeroes behind itself) -> graph-replay safe.
__device__ float    g_buf[2][BUF_FLOATS];
__device__ unsigned g_vmax_u[NIMG];

__device__ __forceinline__ void red4(float* a, float x, float y, float z, float w) {
    asm volatile("red.global.add.v4.f32 [%0], {%1,%2,%3,%4};"
                 :: "l"(a), "f"(x), "f"(y), "f"(z), "f"(w) : "memory");
}

// ---------------------------------------------------------------------------
// hist block body: 64 blocks per image (2 column halves x 32 row chunks).
// One v4 red per pixel pair into parity copy c, tile (tr,tc).
// ---------------------------------------------------------------------------
__device__ __forceinline__ void hist_block(const float* __restrict__ X,
                                           float* __restrict__ buf,
                                           int img0, int hb, int zero_vmax) {
    if (zero_vmax && hb == 0 && threadIdx.x < NIMG) g_vmax_u[threadIdx.x] = 0u;

    const int img_l = hb >> 6;
    const int rest  = hb & 63;
    const int col   = ((rest & 1) << 8) + threadIdx.x;
    const int r0    = (rest >> 1) * CHUNK;

    const float* __restrict__ base =
        X + (size_t)(img0 + img_l) * (HDIM * WDIM) + col;

    float a  = __ldg(base + (size_t)r0 * WDIM);
    float fa = fminf(floorf(a), 254.0f);
    int   ia = (int)fa;
    float wa0 = 0.5f * (1.0f + __cosf(PI_F * (a - fa)));

    const int rmax = min(r0 + CHUNK, HDIM - 1);
    for (int r = r0; r < rmax; ++r) {
        float b  = __ldg(base + (size_t)(r + 1) * WDIM);
        float fb = fminf(floorf(b), 254.0f);
        int   ib = (int)fb;
        float wb0 = 0.5f * (1.0f + __cosf(PI_F * (b - fb)));

        const float wa1 = 1.0f - wa0;
        const float wb1 = 1.0f - wb0;

        const int c  = ((ia & 1) << 1) | (ib & 1);
        const int tr = (ia + 1) >> 1;
        const int tc = (ib + 1) >> 1;
        float* p = buf + ((((c * BATCH + img_l) << 14) + (tr << 7) + tc) << 2);
        red4(p, wa0 * wb0, wa0 * wb1, wa1 * wb0, wa1 * wb1);

        a = b; ia = ib; wa0 = wb0;
    }
}

// ---------------------------------------------------------------------------
// merge block body: 256 blocks per image, one output bin per thread.
// Sums the 4 parity contributions, zeroes the elements it read (bijective
// mapping -> race free), writes out, and folds per-image max via atomicMax.
// ---------------------------------------------------------------------------
__device__ __forceinline__ void merge_block(float* __restrict__ buf,
                                            float* __restrict__ out,
                                            int img0, int mb) {
    const int img_l = mb >> 8;
    const int idx   = ((mb & 255) << 8) + threadIdx.x;   // [0, 65536)
    const int i = idx >> 8;
    const int j = idx & 255;

    float s = 0.0f;
    #pragma unroll
    for (int pr = 0; pr < 2; ++pr) {
        #pragma unroll
        for (int pc = 0; pc < 2; ++pc) {
            const int tr = (i + pr) >> 1;
            const int tc = (j + pc) >> 1;
            if (tr < 128 && tc < 128) {
                const int c    = (pr << 1) | pc;
                const int lane = (((i + pr) & 1) << 1) | ((j + pc) & 1);
                const int off  =
                    ((((c * BATCH + img_l) << 14) + (tr << 7) + tc) << 2) + lane;
                s += buf[off];
                buf[off] = 0.0f;                 // restore scratch to zero
            }
        }
    }
    out[((size_t)(img0 + img_l) << 16) + idx] = s;

    // block max -> atomicMax (values are non-negative: uint bits monotonic)
    float m = s;
    #pragma unroll
    for (int o = 16; o > 0; o >>= 1)
        m = fmaxf(m, __shfl_xor_sync(0xFFFFFFFFu, m, o));
    __shared__ float sm[8];
    if ((threadIdx.x & 31) == 0) sm[threadIdx.x >> 5] = m;
    __syncthreads();
    if (threadIdx.x < 8) {
        m = sm[threadIdx.x];
        #pragma unroll
        for (int o = 4; o > 0; o >>= 1)
            m = fmaxf(m, __shfl_xor_sync(0xFFu, m, o));
        if (threadIdx.x == 0)
            atomicMax(&g_vmax_u[img0 + img_l], __float_as_uint(m));
    }
}

// ---------------------------------------------------------------------------
// Kernels
// ---------------------------------------------------------------------------
__global__ void __launch_bounds__(256) k_hist(const float* __restrict__ X,
                                              int img0, int bufi, int zero_vmax) {
    hist_block(X, g_buf[bufi], img0, blockIdx.x, zero_vmax);
}

// grid = 7680 blocks: bid%5==0 -> hist (1536), else merge (6144). Interleaved
// so merge's cheap LDG/STG work hides in the RED-bound hist blocks' slack.
__global__ void __launch_bounds__(256) k_mixed(const float* __restrict__ X,
                                               float* __restrict__ out,
                                               int himg0, int hbufi,
                                               int mimg0, int mbufi) {
    const int bid = blockIdx.x;
    if (bid % 5 == 0) {
        hist_block(X, g_buf[hbufi], himg0, bid / 5, 0);
    } else {
        const int mb = (bid / 5) * 4 + (bid % 5) - 1;
        merge_block(g_buf[mbufi], out, mimg0, mb);
    }
}

__global__ void __launch_bounds__(256) k_merge(float* __restrict__ out,
                                               int img0, int bufi) {
    merge_block(g_buf[bufi], out, img0, blockIdx.x);
}

__global__ void __launch_bounds__(256) k_norm(float* __restrict__ out) {
    const int img = blockIdx.y;
    const float inv = 1.0f / __uint_as_float(g_vmax_u[img]);
    float4* __restrict__ h4 = reinterpret_cast<float4*>(out + ((size_t)img << 16));
    const int i = blockIdx.x * blockDim.x + threadIdx.x;   // [0, 16384)
    float4 v = h4[i];
    v.x *= inv; v.y *= inv; v.z *= inv; v.w *= inv;
    h4[i] = v;
}

// ---------------------------------------------------------------------------
extern "C" void kernel_launch(void* const* d_in, const int* in_sizes, int n_in,
                              void* d_out, int out_size) {
    const float* X = (const float*)d_in[0];
    float* out = (float*)d_out;

    // software pipeline: hist(b+1) runs concurrently with merge(b)
    k_hist <<<1536, 256>>>(X, 0, 0, 1);
    k_mixed<<<7680, 256>>>(X, out, 24, 1, 0, 0);
    k_mixed<<<7680, 256>>>(X, out, 48, 0, 24, 1);
    k_mixed<<<7680, 256>>>(X, out, 72, 1, 48, 0);
    k_merge<<<6144, 256>>>(out, 72, 1);

    dim3 ngrid((NBINS * NBINS / 4) / 256, NIMG);
    k_norm<<<ngrid, 256>>>(out);
}

// round 6
// speedup vs baseline: 1.3934x; 1.3934x over previous
#include <cuda_runtime.h>
#include <cuda_bf16.h>

#define NBINS 256
#define NIMG  96
#define BATCH 24
#define HDIM  512
#define WDIM  512
#define CHUNK 16
#define PI_F  3.14159265358979323846f

#define TILES_PER_IMG (128 * 128)
#define BUF_FLOATS (4 * BATCH * TILES_PER_IMG * 4)   // 25.2 MB, single buffer

// zero-initialized at load; every call restores it to zero (merge zeroes
// behind itself) -> graph-replay safe.
__device__ float    g_buf[BUF_FLOATS];
__device__ unsigned g_vmax_u[NIMG];

__device__ __forceinline__ void red4(float* a, float x, float y, float z, float w) {
    asm volatile("red.global.add.v4.f32 [%0], {%1,%2,%3,%4};"
                 :: "l"(a), "f"(x), "f"(y), "f"(z), "f"(w) : "memory");
}

// ---------------------------------------------------------------------------
// Kernel 1: soft co-occurrence scatter, ONE v4 red per pixel pair.
// Parity copy c = (ia&1)*2 + (ib&1); tile (tr,tc) = ((ia+1)>>1, (ib+1)>>1).
// Lane order: {wa0*wb0, wa0*wb1, wa1*wb0, wa1*wb1}.
// grid = (WDIM/256, 32, BATCH)
// ---------------------------------------------------------------------------
__global__ void __launch_bounds__(256) k_hist(const float* __restrict__ X,
                                              int img0, int zero_vmax) {
    if (zero_vmax && blockIdx.x == 0 && blockIdx.y == 0 && blockIdx.z == 0 &&
        threadIdx.x < NIMG)
        g_vmax_u[threadIdx.x] = 0u;

    const int img_l = blockIdx.z;
    const int col   = blockIdx.x * blockDim.x + threadIdx.x;
    const int r0    = blockIdx.y * CHUNK;

    const float* __restrict__ base =
        X + (size_t)(img0 + img_l) * (HDIM * WDIM) + col;

    float a  = __ldg(base + (size_t)r0 * WDIM);
    float fa = fminf(floorf(a), 254.0f);
    int   ia = (int)fa;
    float wa0 = 0.5f * (1.0f + __cosf(PI_F * (a - fa)));

    const int rmax = min(r0 + CHUNK, HDIM - 1);
    for (int r = r0; r < rmax; ++r) {
        float b  = __ldg(base + (size_t)(r + 1) * WDIM);
        float fb = fminf(floorf(b), 254.0f);
        int   ib = (int)fb;
        float wb0 = 0.5f * (1.0f + __cosf(PI_F * (b - fb)));

        const float wa1 = 1.0f - wa0;
        const float wb1 = 1.0f - wb0;

        const int c  = ((ia & 1) << 1) | (ib & 1);
        const int tr = (ia + 1) >> 1;
        const int tc = (ib + 1) >> 1;
        float* p = g_buf + ((((c * BATCH + img_l) << 14) + (tr << 7) + tc) << 2);
        red4(p, wa0 * wb0, wa0 * wb1, wa1 * wb0, wa1 * wb1);

        a = b; ia = ib; wa0 = wb0;
    }
}

// ---------------------------------------------------------------------------
// Kernel 2: merge the 4 parity copies into the output histogram.
// Each scratch element is read by exactly ONE thread (bijective map), which
// zeroes it behind itself. Block max folded into g_vmax_u via atomicMax.
// grid = (256, BATCH)
// ---------------------------------------------------------------------------
__global__ void __launch_bounds__(256) k_merge(float* __restrict__ out,
                                               int img0) {
    const int img_l = blockIdx.y;
    const int idx   = blockIdx.x * blockDim.x + threadIdx.x;   // [0, 65536)
    const int i = idx >> 8;
    const int j = idx & 255;

    float s = 0.0f;
    #pragma unroll
    for (int pr = 0; pr < 2; ++pr) {
        #pragma unroll
        for (int pc = 0; pc < 2; ++pc) {
            const int tr = (i + pr) >> 1;
            const int tc = (j + pc) >> 1;
            if (tr < 128 && tc < 128) {
                const int c    = (pr << 1) | pc;
                const int lane = (((i + pr) & 1) << 1) | ((j + pc) & 1);
                const int off  =
                    ((((c * BATCH + img_l) << 14) + (tr << 7) + tc) << 2) + lane;
                s += g_buf[off];
                g_buf[off] = 0.0f;               // restore scratch to zero
            }
        }
    }
    out[((size_t)(img0 + img_l) << 16) + idx] = s;

    // fold block max into per-image max (values >= 0: uint bits monotonic)
    float m = s;
    #pragma unroll
    for (int o = 16; o > 0; o >>= 1)
        m = fmaxf(m, __shfl_xor_sync(0xFFFFFFFFu, m, o));
    __shared__ float sm[8];
    if ((threadIdx.x & 31) == 0) sm[threadIdx.x >> 5] = m;
    __syncthreads();
    if (threadIdx.x < 8) {
        m = sm[threadIdx.x];
        #pragma unroll
        for (int o = 4; o > 0; o >>= 1)
            m = fmaxf(m, __shfl_xor_sync(0xFFu, m, o));
        if (threadIdx.x == 0)
            atomicMax(&g_vmax_u[img0 + img_l], __float_as_uint(m));
    }
}

// ---------------------------------------------------------------------------
// Kernel 3: scale each histogram by 1/vmax.  grid = (64, NIMG)
// ---------------------------------------------------------------------------
__global__ void __launch_bounds__(256) k_norm(float* __restrict__ out) {
    const int img = blockIdx.y;
    const float inv = 1.0f / __uint_as_float(g_vmax_u[img]);
    float4* __restrict__ h4 = reinterpret_cast<float4*>(out + ((size_t)img << 16));
    const int i = blockIdx.x * blockDim.x + threadIdx.x;   // [0, 16384)
    float4 v = h4[i];
    v.x *= inv; v.y *= inv; v.z *= inv; v.w *= inv;
    h4[i] = v;
}

// ---------------------------------------------------------------------------
extern "C" void kernel_launch(void* const* d_in, const int* in_sizes, int n_in,
                              void* d_out, int out_size) {
    const float* X = (const float*)d_in[0];
    float* out = (float*)d_out;

    const dim3 hgrid(WDIM / 256, (HDIM - 1 + CHUNK - 1) / CHUNK, BATCH);
    const dim3 mgrid(65536 / 256, BATCH);

    for (int b = 0; b < NIMG / BATCH; ++b) {
        k_hist <<<hgrid, 256>>>(X, b * BATCH, b == 0);
        k_merge<<<mgrid, 256>>>(out, b * BATCH);
    }

    dim3 ngrid((NBINS * NBINS / 4) / 256, NIMG);
    k_norm<<<ngrid, 256>>>(out);
}

// round 7
// speedup vs baseline: 3.0353x; 2.1784x over previous
#include <cuda_runtime.h>
#include <cuda_bf16.h>

#define NBINS 256
#define NIMG  96
#define BATCH 32            // 3 batches
#define HDIM  512
#define WDIM  512
#define CHUNK 16
#define PI_F  3.14159265358979323846f

#define TILES_PER_IMG (128 * 128)
#define BUF_FLOATS (4 * BATCH * TILES_PER_IMG * 4)   // 33.5 MB

// zero-initialized at load; merge restores it to exactly zero every call
// (block-exclusive coalesced zero-stores) -> graph-replay safe.
__device__ float    g_buf[BUF_FLOATS];
__device__ unsigned g_vmax_u[NIMG];

__device__ __forceinline__ void red4(float* a, float x, float y, float z, float w) {
    asm volatile("red.global.add.v4.f32 [%0], {%1,%2,%3,%4};"
                 :: "l"(a), "f"(x), "f"(y), "f"(z), "f"(w) : "memory");
}

// ---------------------------------------------------------------------------
// Kernel 1: soft co-occurrence scatter, ONE v4 red per pixel pair.
// Parity copy c = (ia&1)*2 + (ib&1); tile (tr,tc) = ((ia+1)>>1, (ib+1)>>1).
// Lane order: {wa0*wb0, wa0*wb1, wa1*wb0, wa1*wb1}.
// grid = (2, 32, BATCH), block = 256
// ---------------------------------------------------------------------------
__global__ void __launch_bounds__(256) k_hist(const float* __restrict__ X,
                                              int img0, int zero_vmax) {
    if (zero_vmax && blockIdx.x == 0 && blockIdx.y == 0 && blockIdx.z == 0 &&
        threadIdx.x < NIMG)
        g_vmax_u[threadIdx.x] = 0u;

    const int img_l = blockIdx.z;
    const int col   = blockIdx.x * blockDim.x + threadIdx.x;
    const int r0    = blockIdx.y * CHUNK;

    const float* __restrict__ base =
        X + (size_t)(img0 + img_l) * (HDIM * WDIM) + col;

    float a  = __ldg(base + (size_t)r0 * WDIM);
    float fa = fminf(floorf(a), 254.0f);
    int   ia = (int)fa;
    float wa0 = 0.5f * (1.0f + __cosf(PI_F * (a - fa)));

    const int rmax = min(r0 + CHUNK, HDIM - 1);
    for (int r = r0; r < rmax; ++r) {
        float b  = __ldg(base + (size_t)(r + 1) * WDIM);
        float fb = fminf(floorf(b), 254.0f);
        int   ib = (int)fb;
        float wb0 = 0.5f * (1.0f + __cosf(PI_F * (b - fb)));

        const float wa1 = 1.0f - wa0;
        const float wb1 = 1.0f - wb0;

        const int c  = ((ia & 1) << 1) | (ib & 1);
        const int tr = (ia + 1) >> 1;
        const int tc = (ib + 1) >> 1;
        float* p = g_buf + ((((c * BATCH + img_l) << 14) + (tr << 7) + tc) << 2);
        red4(p, wa0 * wb0, wa0 * wb1, wa1 * wb0, wa1 * wb1);

        a = b; ia = ib; wa0 = wb0;
    }
}

// ---------------------------------------------------------------------------
// Kernel 2: merge + self-zero + per-image max.
// Block bx handles output rows i0=2*bx, i0+1 (512 threads, one bin each).
// Block-exclusive scratch ownership:
//   pr=0 copies: full float4 tile-row bx          -> float4 zero-stores
//   pr=1 copies: la=1 half of tile-row bx,
//                la=0 half of tile-row bx+1       -> float2 zero-stores
// grid = (128, BATCH), block = 512
// ---------------------------------------------------------------------------
__global__ void __launch_bounds__(512) k_merge(float* __restrict__ out,
                                               int img0) {
    const int img_l = blockIdx.y;
    const int bx    = blockIdx.x;            // tile-row / output-row-pair
    const int t     = threadIdx.x;
    const int di    = t >> 8;
    const int j     = t & 255;
    const int i     = (bx << 1) + di;

    // gather the 4 parity contributions for bin (i, j)
    float s = 0.0f;
    #pragma unroll
    for (int pr = 0; pr < 2; ++pr) {
        #pragma unroll
        for (int pc = 0; pc < 2; ++pc) {
            const int tr = (i + pr) >> 1;
            const int tc = (j + pc) >> 1;
            if (tr < 128 && tc < 128) {
                const int c    = (pr << 1) | pc;
                const int lane = (((i + pr) & 1) << 1) | ((j + pc) & 1);
                s += g_buf[((((c * BATCH + img_l) << 14) + (tr << 7) + tc) << 2) + lane];
            }
        }
    }
    out[((size_t)(img0 + img_l) << 16) + (i << 8) + j] = s;

    __syncthreads();   // all block reads done before zeroing owned region

    // A) pr=0 copies: full float4 tile-row bx (256 stores, coalesced)
    if (t < 256) {
        const int pc = t >> 7;
        const int tc = t & 127;
        float4* p = reinterpret_cast<float4*>(g_buf) +
                    ((pc * BATCH + img_l) << 14) + (bx << 7) + tc;
        *p = make_float4(0.f, 0.f, 0.f, 0.f);
    }
    // B) pr=1 copies: float2 halves (512 stores)
    {
        const int pc   = t >> 8;
        const int half = (t >> 7) & 1;        // 0: la=1 @ bx ; 1: la=0 @ bx+1
        const int tc   = t & 127;
        const int tr   = bx + half;
        if (tr < 128) {
            const int c  = 2 | pc;
            const int la = half ? 0 : 1;
            float2* p = reinterpret_cast<float2*>(g_buf) +
                        (((((c * BATCH + img_l) << 14) + (tr << 7) + tc) << 1) + la);
            *p = make_float2(0.f, 0.f);
        }
    }

    // per-image max (values >= 0: uint bits monotonic)
    float m = s;
    #pragma unroll
    for (int o = 16; o > 0; o >>= 1)
        m = fmaxf(m, __shfl_xor_sync(0xFFFFFFFFu, m, o));
    __shared__ float sm[16];
    if ((t & 31) == 0) sm[t >> 5] = m;
    __syncthreads();
    if (t < 16) {
        m = sm[t];
        #pragma unroll
        for (int o = 8; o > 0; o >>= 1)
            m = fmaxf(m, __shfl_xor_sync(0xFFFFu, m, o));
        if (t == 0)
            atomicMax(&g_vmax_u[img0 + img_l], __float_as_uint(m));
    }
}

// ---------------------------------------------------------------------------
// Kernel 3: scale each histogram by 1/vmax.  grid = (64, NIMG)
// ---------------------------------------------------------------------------
__global__ void __launch_bounds__(256) k_norm(float* __restrict__ out) {
    const int img = blockIdx.y;
    const float inv = 1.0f / __uint_as_float(g_vmax_u[img]);
    float4* __restrict__ h4 = reinterpret_cast<float4*>(out + ((size_t)img << 16));
    const int i = blockIdx.x * blockDim.x + threadIdx.x;   // [0, 16384)
    float4 v = h4[i];
    v.x *= inv; v.y *= inv; v.z *= inv; v.w *= inv;
    h4[i] = v;
}

// ---------------------------------------------------------------------------
extern "C" void kernel_launch(void* const* d_in, const int* in_sizes, int n_in,
                              void* d_out, int out_size) {
    const float* X = (const float*)d_in[0];
    float* out = (float*)d_out;

    const dim3 hgrid(WDIM / 256, (HDIM - 1 + CHUNK - 1) / CHUNK, BATCH);
    const dim3 mgrid(128, BATCH);

    for (int b = 0; b < NIMG / BATCH; ++b) {
        k_hist <<<hgrid, 256>>>(X, b * BATCH, b == 0);
        k_merge<<<mgrid, 512>>>(out, b * BATCH);
    }

    dim3 ngrid((NBINS * NBINS / 4) / 256, NIMG);
    k_norm<<<ngrid, 256>>>(out);
}